// round 15
// baseline (speedup 1.0000x reference)
#include <cuda_runtime.h>
#include <cuda_fp16.h>
#include <cstdint>

// ---------------------------------------------------------------------------
// LinearAttention fused pipeline (fp16 HMMA GEMMs + HMMA ctx, fused softmax_q
// + GN stats; stream-forked GEMM1_q || softmax_k->ctx->weff chain).
// GEMM tile 128x64, occupancy 3 (was 2) to hide sync/load bubbles.
// b=16, c=512, t=4096, heads=8, dh=64, hidden=512
// ---------------------------------------------------------------------------

#define B   16
#define C   512
#define T   4096
#define H   8
#define DH  64
#define HID 512
#define QKV_CH 1536
#define SCALE 0.125f   // 64^-0.5
#define GN_EPS 1e-5f

// Scratch (static device arrays: allocation-free rule)
__device__ __half g_xh[(size_t)B * C * T];                // 67 MB (xh, then y fp16)
__device__ __half g_qh[(size_t)B * HID * T];              // 67 MB (softmaxed q)
__device__ __half g_kh[(size_t)B * HID * T];              // 67 MB
__device__ __half g_vh[(size_t)B * HID * T];              // 67 MB
__device__ __half g_wqkvh[(size_t)QKV_CH * C];            // 1.5 MB
__device__ __half g_weffh[(size_t)B * C * C];             // 8 MB
__device__ float  g_ctx[(size_t)B * H * DH * DH];         // 2 MB
__device__ float  g_stats[B * 256 * 2];
__device__ float  g_mr[B * 2];

// ========================= helpers =========================================
__device__ __forceinline__ uint32_t smem_u32(const void* p) {
    uint32_t a;
    asm("{ .reg .u64 t; cvta.to.shared.u64 t, %1; cvt.u32.u64 %0, t; }"
        : "=r"(a) : "l"(p));
    return a;
}

__device__ __forceinline__ void cp_async16(uint32_t smem_dst, const void* gsrc) {
    asm volatile("cp.async.cg.shared.global [%0], [%1], 16;"
                 :: "r"(smem_dst), "l"(gsrc));
}
__device__ __forceinline__ void cp_commit() {
    asm volatile("cp.async.commit_group;" ::: "memory");
}
template <int N>
__device__ __forceinline__ void cp_wait() {
    asm volatile("cp.async.wait_group %0;" :: "n"(N) : "memory");
}

__device__ __forceinline__ void ldsm_x4(uint32_t* r, uint32_t addr) {
    asm volatile("ldmatrix.sync.aligned.m8n8.x4.shared.b16 {%0,%1,%2,%3}, [%4];"
                 : "=r"(r[0]), "=r"(r[1]), "=r"(r[2]), "=r"(r[3]) : "r"(addr));
}
__device__ __forceinline__ void ldsm_x4_trans(uint32_t* r, uint32_t addr) {
    asm volatile("ldmatrix.sync.aligned.m8n8.x4.trans.shared.b16 {%0,%1,%2,%3}, [%4];"
                 : "=r"(r[0]), "=r"(r[1]), "=r"(r[2]), "=r"(r[3]) : "r"(addr));
}

__device__ __forceinline__ void mma16n8k16(float* c, const uint32_t* a,
                                           const uint32_t* b) {
    asm volatile(
        "mma.sync.aligned.m16n8k16.row.col.f32.f16.f16.f32 "
        "{%0,%1,%2,%3}, {%4,%5,%6,%7}, {%8,%9}, {%0,%1,%2,%3};"
        : "+f"(c[0]), "+f"(c[1]), "+f"(c[2]), "+f"(c[3])
        : "r"(a[0]), "r"(a[1]), "r"(a[2]), "r"(a[3]),
          "r"(b[0]), "r"(b[1]));
}

// ------------------------- block reduce helper -----------------------------
__device__ __forceinline__ float blockReduceSum(float v, float* sm) {
    __syncthreads();
    #pragma unroll
    for (int o = 16; o; o >>= 1) v += __shfl_down_sync(0xffffffffu, v, o);
    int lane = threadIdx.x & 31, w = threadIdx.x >> 5;
    if (lane == 0) sm[w] = v;
    __syncthreads();
    if (w == 0) {
        v = (lane < (int)(blockDim.x >> 5)) ? sm[lane] : 0.f;
        #pragma unroll
        for (int o = 16; o; o >>= 1) v += __shfl_down_sync(0xffffffffu, v, o);
        if (lane == 0) sm[0] = v;
    }
    __syncthreads();
    return sm[0];
}

__device__ __forceinline__ float blockReduceMax(float v, float* sm) {
    __syncthreads();
    #pragma unroll
    for (int o = 16; o; o >>= 1) v = fmaxf(v, __shfl_down_sync(0xffffffffu, v, o));
    int lane = threadIdx.x & 31, w = threadIdx.x >> 5;
    if (lane == 0) sm[w] = v;
    __syncthreads();
    if (w == 0) {
        v = (lane < (int)(blockDim.x >> 5)) ? sm[lane] : -1e30f;
        #pragma unroll
        for (int o = 16; o; o >>= 1) v = fmaxf(v, __shfl_down_sync(0xffffffffu, v, o));
        if (lane == 0) sm[0] = v;
    }
    __syncthreads();
    return sm[0];
}

// ========================= fp16 HMMA GEMM ==================================
// Tile 128x64x32, 8 warps (2m x 4n) of 64x16, 4-stage cp.async, occupancy 3.
#define BM 128
#define BN 64
#define BK 32
#define ASH 40     // halves per A row (pad 8)
#define BSH 72     // halves per B row (pad 8)
#define A_BYTES (BM * ASH * 2)            // 10240
#define B_BYTES (BK * BSH * 2)            // 4608
#define STAGE_BYTES (A_BYTES + B_BYTES)   // 14848
#define NSTAGE 4
#define TGEMM_SMEM (NSTAGE * STAGE_BYTES) // 59392

// MODE 1: qkv epilogue (q softmax -> qh, k/v -> kh/vh), rows offset by bm0.
// MODE 2: y fp16 -> q_out, bias, GN partial stats.
template <int MODE>
__global__ __launch_bounds__(256, 3)
void hgemm(const __half* __restrict__ A, long strideA,
           const __half* __restrict__ X, long strideX,
           int bm0,
           int M, int N, int K, const float* __restrict__ bias,
           __half* __restrict__ q_out, __half* __restrict__ k_out,
           __half* __restrict__ v_out, float* __restrict__ stats)
{
    extern __shared__ char dsm[];
    __shared__ float redsm[32];
    const int tid = threadIdx.x;
    const int wid = tid >> 5;
    const int lane = tid & 31;
    const int gid = lane >> 2;
    const int tg  = lane & 3;
    const int lg  = lane >> 3;
    const int lr  = lane & 7;
    const int b  = blockIdx.z;
    const int bm = bm0 + blockIdx.y * BM, bn = blockIdx.x * BN;
    const __half* Ab = A + (long)b * strideA + (long)bm * K;
    const __half* Xb = X + (long)b * strideX + bn;

    const uint32_t smem0 = smem_u32(dsm);
    const int warpM = (wid >> 2) * 64;     // 0 or 64
    const int warpN = (wid & 3) * 16;      // 0,16,32,48

    const uint32_t a_ldsm = (uint32_t)(((warpM + (lg & 1) * 8 + lr) * ASH
                                        + (lg >> 1) * 8) * 2);
    const uint32_t b_ldsm = (uint32_t)A_BYTES
        + (uint32_t)((((lg & 1) * 8 + lr) * BSH + warpN + (lg >> 1) * 8) * 2);

    float acc[4][2][4];
    #pragma unroll
    for (int mt = 0; mt < 4; mt++)
        #pragma unroll
        for (int nt = 0; nt < 2; nt++)
            #pragma unroll
            for (int r = 0; r < 4; r++) acc[mt][nt][r] = 0.f;

    const int niter = K / BK;   // 16

    auto load_stage = [&](int it) {
        const int k0 = it * BK;
        const uint32_t sb = smem0 + (it % NSTAGE) * STAGE_BYTES;
        #pragma unroll
        for (int i = 0; i < 2; i++) {          // A: 512 chunks of 8 halves
            int v = tid + i * 256;
            int row = v >> 2, c8 = (v & 3) * 8;
            cp_async16(sb + (uint32_t)((row * ASH + c8) * 2),
                       &Ab[(long)row * K + k0 + c8]);
        }
        {                                      // B: 256 chunks (1/thread)
            int kr = tid >> 3, c8 = (tid & 7) * 8;
            cp_async16(sb + (uint32_t)A_BYTES + (uint32_t)((kr * BSH + c8) * 2),
                       &Xb[(long)(k0 + kr) * N + c8]);
        }
        cp_commit();
    };

    load_stage(0);
    load_stage(1);
    load_stage(2);

    for (int it = 0; it < niter; it++) {
        if (it + 3 < niter) { load_stage(it + 3); cp_wait<3>(); }
        else {
            int rem = niter - 1 - it;
            if (rem >= 3) cp_wait<3>();
            else if (rem == 2) cp_wait<2>();
            else if (rem == 1) cp_wait<1>();
            else cp_wait<0>();
        }
        __syncthreads();

        const uint32_t sb = smem0 + (it % NSTAGE) * STAGE_BYTES;

        #pragma unroll
        for (int kk = 0; kk < 2; kk++) {
            uint32_t afr[4][4], bfr[2][2];
            #pragma unroll
            for (int mt = 0; mt < 4; mt++)
                ldsm_x4(afr[mt], sb + a_ldsm
                        + (uint32_t)((mt * 16 * ASH + kk * 16) * 2));
            {
                uint32_t r4[4];
                ldsm_x4_trans(r4, sb + b_ldsm
                              + (uint32_t)((kk * 16 * BSH) * 2));
                bfr[0][0] = r4[0]; bfr[0][1] = r4[1];
                bfr[1][0] = r4[2]; bfr[1][1] = r4[3];
            }
            #pragma unroll
            for (int mt = 0; mt < 4; mt++)
                #pragma unroll
                for (int nt = 0; nt < 2; nt++)
                    mma16n8k16(acc[mt][nt], afr[mt], bfr[nt]);
        }
        __syncthreads();
    }

    if (MODE == 1) {
        const int ch0 = bm + warpM;
        if (ch0 < HID) {
            float mxA[2], mxB[2], scA[2], scB[2];
            #pragma unroll
            for (int nt = 0; nt < 2; nt++) {
                float a = -1e30f, bb = -1e30f;
                #pragma unroll
                for (int mt = 0; mt < 4; mt++) {
                    a  = fmaxf(a,  fmaxf(acc[mt][nt][0], acc[mt][nt][2]));
                    bb = fmaxf(bb, fmaxf(acc[mt][nt][1], acc[mt][nt][3]));
                }
                #pragma unroll
                for (int o = 4; o <= 16; o <<= 1) {
                    a  = fmaxf(a,  __shfl_xor_sync(0xffffffffu, a, o));
                    bb = fmaxf(bb, __shfl_xor_sync(0xffffffffu, bb, o));
                }
                mxA[nt] = a; mxB[nt] = bb;
            }
            #pragma unroll
            for (int nt = 0; nt < 2; nt++) {
                float sa = 0.f, sb2 = 0.f;
                #pragma unroll
                for (int mt = 0; mt < 4; mt++) {
                    acc[mt][nt][0] = __expf(acc[mt][nt][0] - mxA[nt]);
                    acc[mt][nt][2] = __expf(acc[mt][nt][2] - mxA[nt]);
                    sa += acc[mt][nt][0] + acc[mt][nt][2];
                    acc[mt][nt][1] = __expf(acc[mt][nt][1] - mxB[nt]);
                    acc[mt][nt][3] = __expf(acc[mt][nt][3] - mxB[nt]);
                    sb2 += acc[mt][nt][1] + acc[mt][nt][3];
                }
                #pragma unroll
                for (int o = 4; o <= 16; o <<= 1) {
                    sa  += __shfl_xor_sync(0xffffffffu, sa, o);
                    sb2 += __shfl_xor_sync(0xffffffffu, sb2, o);
                }
                scA[nt] = SCALE / sa; scB[nt] = SCALE / sb2;
            }
            __half* qb = q_out + (long)b * HID * T;
            #pragma unroll
            for (int mt = 0; mt < 4; mt++) {
                int ch = ch0 + mt * 16 + gid;
                #pragma unroll
                for (int nt = 0; nt < 2; nt++) {
                    int t = bn + warpN + nt * 8 + tg * 2;
                    *(__half2*)&qb[(long)ch * T + t] =
                        __floats2half2_rn(acc[mt][nt][0] * scA[nt],
                                          acc[mt][nt][1] * scB[nt]);
                    *(__half2*)&qb[(long)(ch + 8) * T + t] =
                        __floats2half2_rn(acc[mt][nt][2] * scA[nt],
                                          acc[mt][nt][3] * scB[nt]);
                }
            }
        } else {
            __half* dst = (ch0 < 2 * HID) ? k_out : v_out;
            const int chbase = ch0 - ((ch0 < 2 * HID) ? HID : 2 * HID);
            __half* db = dst + (long)b * HID * T;
            #pragma unroll
            for (int mt = 0; mt < 4; mt++) {
                int ch = chbase + mt * 16 + gid;
                #pragma unroll
                for (int nt = 0; nt < 2; nt++) {
                    int t = bn + warpN + nt * 8 + tg * 2;
                    *(__half2*)&db[(long)ch * T + t] =
                        __floats2half2_rn(acc[mt][nt][0], acc[mt][nt][1]);
                    *(__half2*)&db[(long)(ch + 8) * T + t] =
                        __floats2half2_rn(acc[mt][nt][2], acc[mt][nt][3]);
                }
            }
        }
    } else {
        // ---- GEMM2 epilogue: y fp16 + bias, GN partial sums (fp32) ----
        float ls = 0.f, lss = 0.f;
        __half* yb = q_out + (long)b * C * T;
        #pragma unroll
        for (int mt = 0; mt < 4; mt++) {
            int row0 = bm + warpM + mt * 16 + gid;
            float bv0 = bias[row0];
            float bv1 = bias[row0 + 8];
            #pragma unroll
            for (int nt = 0; nt < 2; nt++) {
                int col = bn + warpN + nt * 8 + tg * 2;
                float o0x = acc[mt][nt][0] + bv0, o0y = acc[mt][nt][1] + bv0;
                float o1x = acc[mt][nt][2] + bv1, o1y = acc[mt][nt][3] + bv1;
                ls  += o0x + o0y + o1x + o1y;
                lss += o0x * o0x + o0y * o0y + o1x * o1x + o1y * o1y;
                *(__half2*)&yb[(long)row0 * T + col] = __floats2half2_rn(o0x, o0y);
                *(__half2*)&yb[(long)(row0 + 8) * T + col] = __floats2half2_rn(o1x, o1y);
            }
        }
        float S  = blockReduceSum(ls, redsm);
        float SS = blockReduceSum(lss, redsm);
        if (tid == 0) {
            int tile = blockIdx.y * gridDim.x + blockIdx.x;   // < 256
            stats[((long)b * 256 + tile) * 2 + 0] = S;
            stats[((long)b * 256 + tile) * 2 + 1] = SS;
        }
    }
}

// ================= HMMA context: ctx[b,h] = k @ v^T (64x64) ================
#define CT 64
#define CROW 72
#define CTILE_BYTES (DH * CROW * 2)        // 9216
#define CSTAGE_BYTES (2 * CTILE_BYTES)     // 18432
#define CSTAGES 4
#define CTX_SMEM (CSTAGES * CSTAGE_BYTES)  // 73728

__global__ __launch_bounds__(256, 1)
void ctx_hmma(const __half* __restrict__ kh, const __half* __restrict__ vh,
              float* __restrict__ ctx)
{
    extern __shared__ char dsm[];
    const int tid = threadIdx.x;
    const int wid = tid >> 5;
    const int lane = tid & 31;
    const int gid = lane >> 2;
    const int tg  = lane & 3;
    const int lg  = lane >> 3;
    const int lr  = lane & 7;
    const int bh = blockIdx.x;
    const int b = bh >> 3, h = bh & 7;
    const __half* kb = kh + ((long)b * HID + h * DH) * T;
    const __half* vb = vh + ((long)b * HID + h * DH) * T;

    const uint32_t smem0 = smem_u32(dsm);
    const int warpM = (wid >> 2) * 32;
    const int warpN = (wid & 3) * 16;

    const uint32_t a_base = (uint32_t)(((warpM + (lg & 1) * 8 + lr) * CROW
                                        + (lg >> 1) * 8) * 2);
    const int brow = warpN + (lane & 7) + ((lane >> 4) << 3);
    const uint32_t b_base = (uint32_t)CTILE_BYTES
        + (uint32_t)((brow * CROW + ((lane >> 3) & 1) * 8) * 2);

    float acc[2][2][4];
    #pragma unroll
    for (int mi = 0; mi < 2; mi++)
        #pragma unroll
        for (int ni = 0; ni < 2; ni++)
            #pragma unroll
            for (int r = 0; r < 4; r++) acc[mi][ni][r] = 0.f;

    const int nchunks = T / CT;            // 64

    auto load = [&](int ch) {
        const int t0 = ch * CT;
        const uint32_t sb = smem0 + (ch % CSTAGES) * CSTAGE_BYTES;
        #pragma unroll
        for (int i = 0; i < 4; i++) {
            int v = tid + i * 256;
            int mat = v >> 9;
            int r = (v >> 3) & 63;
            int c8 = (v & 7) * 8;
            const __half* gp = (mat ? vb : kb) + (long)r * T + t0 + c8;
            cp_async16(sb + (uint32_t)(mat * CTILE_BYTES + r * (CROW * 2) + c8 * 2),
                       gp);
        }
        cp_commit();
    };

    load(0); load(1); load(2);

    for (int ch = 0; ch < nchunks; ch++) {
        if (ch + 3 < nchunks) { load(ch + 3); cp_wait<3>(); }
        else {
            int rem = nchunks - 1 - ch;
            if (rem == 2) cp_wait<2>();
            else if (rem == 1) cp_wait<1>();
            else if (rem == 0) cp_wait<0>();
            else cp_wait<3>();
        }
        __syncthreads();

        const uint32_t sb = smem0 + (ch % CSTAGES) * CSTAGE_BYTES;
        #pragma unroll
        for (int kk = 0; kk < 4; kk++) {
            uint32_t afr[2][4], bfr4[4];
            #pragma unroll
            for (int mi = 0; mi < 2; mi++)
                ldsm_x4(afr[mi], sb + a_base
                        + (uint32_t)((mi * 16 * CROW + kk * 16) * 2));
            ldsm_x4(bfr4, sb + b_base + (uint32_t)(kk * 16 * 2));
            #pragma unroll
            for (int mi = 0; mi < 2; mi++) {
                mma16n8k16(acc[mi][0], afr[mi], &bfr4[0]);
                mma16n8k16(acc[mi][1], afr[mi], &bfr4[2]);
            }
        }
        __syncthreads();
    }

    float* cp = ctx + (long)bh * (DH * DH);
    #pragma unroll
    for (int mi = 0; mi < 2; mi++) {
        int d0 = warpM + mi * 16 + gid;
        #pragma unroll
        for (int ni = 0; ni < 2; ni++) {
            int e = warpN + ni * 8 + tg * 2;
            *(float2*)&cp[d0 * DH + e]       = make_float2(acc[mi][ni][0], acc[mi][ni][1]);
            *(float2*)&cp[(d0 + 8) * DH + e] = make_float2(acc[mi][ni][2], acc[mi][ni][3]);
        }
    }
}

// --------------------- fp32 -> fp16 convert pass ----------------------------
__global__ __launch_bounds__(256)
void conv_half(const float* __restrict__ in, __half* __restrict__ out, int n4)
{
    int i = blockIdx.x * 256 + threadIdx.x;
    if (i >= n4) return;
    float4 v = ((const float4*)in)[i];
    ((__half2*)out)[2 * i]     = __floats2half2_rn(v.x, v.y);
    ((__half2*)out)[2 * i + 1] = __floats2half2_rn(v.z, v.w);
}

// --------------------- softmax over time dim (k), fp16 in/out ---------------
__global__ __launch_bounds__(256)
void softmax_k(__half* __restrict__ kh)
{
    __shared__ float sm[32];
    int r = blockIdx.x;              // b*512 + c
    int b = r >> 9, c = r & 511;
    __half2* row = (__half2*)(kh + ((long)b * HID + c) * T);
    int tid = threadIdx.x;

    float v[16];
    float mx = -1e30f;
    #pragma unroll
    for (int i = 0; i < 8; i++) {
        float2 f = __half22float2(row[tid + i * 256]);
        v[2 * i] = f.x; v[2 * i + 1] = f.y;
        mx = fmaxf(mx, fmaxf(f.x, f.y));
    }
    mx = blockReduceMax(mx, sm);
    float s = 0.f;
    #pragma unroll
    for (int i = 0; i < 16; i++) { v[i] = __expf(v[i] - mx); s += v[i]; }
    s = blockReduceSum(s, sm);
    float inv = 1.f / s;
    #pragma unroll
    for (int i = 0; i < 8; i++)
        row[tid + i * 256] = __floats2half2_rn(v[2 * i] * inv, v[2 * i + 1] * inv);
}

// ----- Weff[b][o][h*64+d] = sum_e Wout[o][h*64+e] * ctx[b][h][d][e] -> half --
__global__ __launch_bounds__(256)
void make_weff(const float* __restrict__ ctx, const float* __restrict__ Wout,
               __half* __restrict__ weffh)
{
    __shared__ float cs[DH][DH];   // ctx[d][e]
    int b = blockIdx.x, h = blockIdx.y;
    const float* c = ctx + (long)(b * H + h) * (DH * DH);
    for (int i = threadIdx.x; i < DH * DH; i += 256) cs[i >> 6][i & 63] = c[i];
    __syncthreads();

    #pragma unroll
    for (int oo = 0; oo < 2; oo++) {
        int o = threadIdx.x + oo * 256;
        float w[DH];
        #pragma unroll
        for (int e = 0; e < DH; e++) w[e] = Wout[(long)o * C + h * DH + e];
        for (int d = 0; d < DH; d++) {
            float s = 0.f;
            #pragma unroll
            for (int e = 0; e < DH; e++) s = fmaf(w[e], cs[d][e], s);
            weffh[((long)b * C + o) * C + h * DH + d] = __float2half(s);
        }
    }
}

// --------------------- GroupNorm finalize + normalize -----------------------
__global__ __launch_bounds__(256)
void gn_finalize(const float* __restrict__ stats, float* __restrict__ mr)
{
    __shared__ float sm[32];
    int b = blockIdx.x;
    float s  = stats[(b * 256 + threadIdx.x) * 2 + 0];
    float ss = stats[(b * 256 + threadIdx.x) * 2 + 1];
    float S  = blockReduceSum(s, sm);
    float SS = blockReduceSum(ss, sm);
    if (threadIdx.x == 0) {
        const float n = (float)((long)C * T);
        float mean = S / n;
        float var  = SS / n - mean * mean;
        mr[b * 2 + 0] = mean;
        mr[b * 2 + 1] = rsqrtf(var + GN_EPS);
    }
}

__global__ __launch_bounds__(256)
void gn_norm(const __half* __restrict__ yh, const float* __restrict__ mr,
             const float* __restrict__ gw, const float* __restrict__ gb,
             float* __restrict__ out)
{
    int b = blockIdx.y;
    long base = (long)b * C * T;
    int idx = (blockIdx.x * 256 + threadIdx.x) * 4;
    int c = idx >> 12;                 // / 4096
    float mean = mr[b * 2 + 0], rstd = mr[b * 2 + 1];
    float g   = gw[c] * rstd;
    float beta = gb[c] - mean * g;
    float2 f0 = __half22float2(*(const __half2*)&yh[base + idx]);
    float2 f1 = __half22float2(*(const __half2*)&yh[base + idx + 2]);
    float4 v;
    v.x = fmaf(f0.x, g, beta);
    v.y = fmaf(f0.y, g, beta);
    v.z = fmaf(f1.x, g, beta);
    v.w = fmaf(f1.y, g, beta);
    *(float4*)&out[base + idx] = v;
}

// ---------------------------------------------------------------------------
extern "C" void kernel_launch(void* const* d_in, const int* in_sizes, int n_in,
                              void* d_out, int out_size)
{
    const float* x     = (const float*)d_in[0];
    const float* Wqkv  = (const float*)d_in[1];
    const float* Wout  = (const float*)d_in[2];
    const float* bout  = (const float*)d_in[3];
    const float* gnw   = (const float*)d_in[4];
    const float* gnb   = (const float*)d_in[5];
    float* out = (float*)d_out;

    float *ctx, *stats, *mr;
    __half *xh, *qh, *kh, *vh, *wqkvh, *weffh;
    cudaGetSymbolAddress((void**)&ctx,   g_ctx);
    cudaGetSymbolAddress((void**)&stats, g_stats);
    cudaGetSymbolAddress((void**)&mr,    g_mr);
    cudaGetSymbolAddress((void**)&xh,    g_xh);
    cudaGetSymbolAddress((void**)&qh,    g_qh);
    cudaGetSymbolAddress((void**)&kh,    g_kh);
    cudaGetSymbolAddress((void**)&vh,    g_vh);
    cudaGetSymbolAddress((void**)&wqkvh, g_wqkvh);
    cudaGetSymbolAddress((void**)&weffh, g_weffh);

    __half* yh = xh;   // xh dead after GEMM1; reuse as fp16 y

    cudaFuncSetAttribute(hgemm<1>,
                         cudaFuncAttributeMaxDynamicSharedMemorySize, TGEMM_SMEM);
    cudaFuncSetAttribute(hgemm<2>,
                         cudaFuncAttributeMaxDynamicSharedMemorySize, TGEMM_SMEM);
    cudaFuncSetAttribute(ctx_hmma,
                         cudaFuncAttributeMaxDynamicSharedMemorySize, CTX_SMEM);

    // side stream for GEMM1_q || (softmax_k -> ctx -> weff); serial fallback
    cudaStream_t s2 = 0;
    cudaEvent_t evA = 0, evB = 0;
    bool forked = (cudaStreamCreateWithFlags(&s2, cudaStreamNonBlocking) == cudaSuccess);
    if (forked) forked = (cudaEventCreateWithFlags(&evA, cudaEventDisableTiming) == cudaSuccess);
    if (forked) forked = (cudaEventCreateWithFlags(&evB, cudaEventDisableTiming) == cudaSuccess);

    // 0) convert inputs to fp16
    conv_half<<<(B * C * T / 4 + 255) / 256, 256>>>(x, xh, B * C * T / 4);
    conv_half<<<(QKV_CH * C / 4 + 255) / 256, 256>>>(Wqkv, wqkvh, QKV_CH * C / 4);

    // 1a) k/v portion of qkv GEMM (channels 512..1535)
    hgemm<1><<<dim3(T / BN, 8, B), 256, TGEMM_SMEM>>>(
        wqkvh, 0L, xh, (long)C * T, HID,
        QKV_CH, T, C, nullptr, qh, kh, vh, nullptr);

    if (forked) {
        cudaEventRecord(evA, 0);
        cudaStreamWaitEvent(s2, evA, 0);
        hgemm<1><<<dim3(T / BN, 4, B), 256, TGEMM_SMEM, s2>>>(
            wqkvh, 0L, xh, (long)C * T, 0,
            QKV_CH, T, C, nullptr, qh, kh, vh, nullptr);
        cudaEventRecord(evB, s2);
    } else {
        hgemm<1><<<dim3(T / BN, 4, B), 256, TGEMM_SMEM>>>(
            wqkvh, 0L, xh, (long)C * T, 0,
            QKV_CH, T, C, nullptr, qh, kh, vh, nullptr);
    }

    // 2-4) k chain (depends only on kh/vh)
    softmax_k<<<B * HID, 256>>>(kh);
    ctx_hmma<<<B * H, 256, CTX_SMEM>>>(kh, vh, ctx);
    make_weff<<<dim3(B, H), 256>>>(ctx, Wout, weffh);

    if (forked) cudaStreamWaitEvent(0, evB, 0);

    // 5) y = Weff @ q + b_out (fp16 y into reused xh), fused GN partial stats
    hgemm<2><<<dim3(T / BN, C / BM, B), 256, TGEMM_SMEM>>>(
        weffh, (long)C * C, qh, (long)HID * T, 0,
        C, T, C, bout, yh, nullptr, nullptr, stats);

    // 6) GroupNorm finalize + apply
    gn_finalize<<<B, 256>>>(stats, mr);
    gn_norm<<<dim3((C * T) / 1024, B), 256>>>(yh, mr, gnw, gnb, out);
}

// round 16
// speedup vs baseline: 1.2097x; 1.2097x over previous
#include <cuda_runtime.h>
#include <cuda_fp16.h>
#include <cstdint>

// ---------------------------------------------------------------------------
// LinearAttention fused pipeline (fp16 HMMA GEMMs + HMMA ctx, fused softmax_q
// + GN stats; stream-forked GEMM1_q || softmax_k->ctx->weff chain).
// GEMM tile 128x128, occupancy 2, single __syncthreads per K-iter.
// b=16, c=512, t=4096, heads=8, dh=64, hidden=512
// ---------------------------------------------------------------------------

#define B   16
#define C   512
#define T   4096
#define H   8
#define DH  64
#define HID 512
#define QKV_CH 1536
#define SCALE 0.125f   // 64^-0.5
#define GN_EPS 1e-5f

// Scratch (static device arrays: allocation-free rule)
__device__ __half g_xh[(size_t)B * C * T];                // 67 MB (xh, then y fp16)
__device__ __half g_qh[(size_t)B * HID * T];              // 67 MB (softmaxed q)
__device__ __half g_kh[(size_t)B * HID * T];              // 67 MB
__device__ __half g_vh[(size_t)B * HID * T];              // 67 MB
__device__ __half g_wqkvh[(size_t)QKV_CH * C];            // 1.5 MB
__device__ __half g_weffh[(size_t)B * C * C];             // 8 MB
__device__ float  g_ctx[(size_t)B * H * DH * DH];         // 2 MB
__device__ float  g_stats[B * 128 * 2];
__device__ float  g_mr[B * 2];

// ========================= helpers =========================================
__device__ __forceinline__ uint32_t smem_u32(const void* p) {
    uint32_t a;
    asm("{ .reg .u64 t; cvta.to.shared.u64 t, %1; cvt.u32.u64 %0, t; }"
        : "=r"(a) : "l"(p));
    return a;
}

__device__ __forceinline__ void cp_async16(uint32_t smem_dst, const void* gsrc) {
    asm volatile("cp.async.cg.shared.global [%0], [%1], 16;"
                 :: "r"(smem_dst), "l"(gsrc));
}
__device__ __forceinline__ void cp_commit() {
    asm volatile("cp.async.commit_group;" ::: "memory");
}
template <int N>
__device__ __forceinline__ void cp_wait() {
    asm volatile("cp.async.wait_group %0;" :: "n"(N) : "memory");
}

__device__ __forceinline__ void ldsm_x4(uint32_t* r, uint32_t addr) {
    asm volatile("ldmatrix.sync.aligned.m8n8.x4.shared.b16 {%0,%1,%2,%3}, [%4];"
                 : "=r"(r[0]), "=r"(r[1]), "=r"(r[2]), "=r"(r[3]) : "r"(addr));
}
__device__ __forceinline__ void ldsm_x4_trans(uint32_t* r, uint32_t addr) {
    asm volatile("ldmatrix.sync.aligned.m8n8.x4.trans.shared.b16 {%0,%1,%2,%3}, [%4];"
                 : "=r"(r[0]), "=r"(r[1]), "=r"(r[2]), "=r"(r[3]) : "r"(addr));
}

__device__ __forceinline__ void mma16n8k16(float* c, const uint32_t* a,
                                           const uint32_t* b) {
    asm volatile(
        "mma.sync.aligned.m16n8k16.row.col.f32.f16.f16.f32 "
        "{%0,%1,%2,%3}, {%4,%5,%6,%7}, {%8,%9}, {%0,%1,%2,%3};"
        : "+f"(c[0]), "+f"(c[1]), "+f"(c[2]), "+f"(c[3])
        : "r"(a[0]), "r"(a[1]), "r"(a[2]), "r"(a[3]),
          "r"(b[0]), "r"(b[1]));
}

// ------------------------- block reduce helper -----------------------------
__device__ __forceinline__ float blockReduceSum(float v, float* sm) {
    __syncthreads();
    #pragma unroll
    for (int o = 16; o; o >>= 1) v += __shfl_down_sync(0xffffffffu, v, o);
    int lane = threadIdx.x & 31, w = threadIdx.x >> 5;
    if (lane == 0) sm[w] = v;
    __syncthreads();
    if (w == 0) {
        v = (lane < (int)(blockDim.x >> 5)) ? sm[lane] : 0.f;
        #pragma unroll
        for (int o = 16; o; o >>= 1) v += __shfl_down_sync(0xffffffffu, v, o);
        if (lane == 0) sm[0] = v;
    }
    __syncthreads();
    return sm[0];
}

__device__ __forceinline__ float blockReduceMax(float v, float* sm) {
    __syncthreads();
    #pragma unroll
    for (int o = 16; o; o >>= 1) v = fmaxf(v, __shfl_down_sync(0xffffffffu, v, o));
    int lane = threadIdx.x & 31, w = threadIdx.x >> 5;
    if (lane == 0) sm[w] = v;
    __syncthreads();
    if (w == 0) {
        v = (lane < (int)(blockDim.x >> 5)) ? sm[lane] : -1e30f;
        #pragma unroll
        for (int o = 16; o; o >>= 1) v = fmaxf(v, __shfl_down_sync(0xffffffffu, v, o));
        if (lane == 0) sm[0] = v;
    }
    __syncthreads();
    return sm[0];
}

// ========================= fp16 HMMA GEMM ==================================
// Tile 128x128x32, 8 warps (2m x 4n) of 64x32, 4-stage cp.async, occupancy 2,
// ONE __syncthreads per K-iter (load for stage it+3 issued after the barrier;
// that stage was last read at iter it-1, which the barrier orders).
#define BM 128
#define BN 128
#define BK 32
#define ASH 40     // halves per A row (pad 8)
#define BSH 136    // halves per B row (pad 8)
#define A_BYTES (BM * ASH * 2)            // 10240
#define B_BYTES (BK * BSH * 2)            // 8704
#define STAGE_BYTES (A_BYTES + B_BYTES)   // 18944
#define NSTAGE 4
#define TGEMM_SMEM (NSTAGE * STAGE_BYTES) // 75776

// MODE 1: qkv epilogue (q softmax -> qh, k/v -> kh/vh), rows offset by bm0.
// MODE 2: y fp16 -> q_out, bias, GN partial stats.
template <int MODE>
__global__ __launch_bounds__(256, 2)
void hgemm(const __half* __restrict__ A, long strideA,
           const __half* __restrict__ X, long strideX,
           int bm0,
           int M, int N, int K, const float* __restrict__ bias,
           __half* __restrict__ q_out, __half* __restrict__ k_out,
           __half* __restrict__ v_out, float* __restrict__ stats)
{
    extern __shared__ char dsm[];
    __shared__ float redsm[32];
    const int tid = threadIdx.x;
    const int wid = tid >> 5;
    const int lane = tid & 31;
    const int gid = lane >> 2;
    const int tg  = lane & 3;
    const int lg  = lane >> 3;
    const int lr  = lane & 7;
    const int b  = blockIdx.z;
    const int bm = bm0 + blockIdx.y * BM, bn = blockIdx.x * BN;
    const __half* Ab = A + (long)b * strideA + (long)bm * K;
    const __half* Xb = X + (long)b * strideX + bn;

    const uint32_t smem0 = smem_u32(dsm);
    const int warpM = (wid >> 2) * 64;     // 0 or 64
    const int warpN = (wid & 3) * 32;      // 0,32,64,96

    const uint32_t a_ldsm = (uint32_t)(((warpM + (lg & 1) * 8 + lr) * ASH
                                        + (lg >> 1) * 8) * 2);
    const uint32_t b_ldsm = (uint32_t)A_BYTES
        + (uint32_t)((((lg & 1) * 8 + lr) * BSH + warpN + (lg >> 1) * 8) * 2);

    float acc[4][4][4];
    #pragma unroll
    for (int mt = 0; mt < 4; mt++)
        #pragma unroll
        for (int nt = 0; nt < 4; nt++)
            #pragma unroll
            for (int r = 0; r < 4; r++) acc[mt][nt][r] = 0.f;

    const int niter = K / BK;   // 16

    auto load_stage = [&](int it) {
        const int k0 = it * BK;
        const uint32_t sb = smem0 + (it % NSTAGE) * STAGE_BYTES;
        #pragma unroll
        for (int i = 0; i < 2; i++) {          // A: 512 chunks of 8 halves
            int v = tid + i * 256;
            int row = v >> 2, c8 = (v & 3) * 8;
            cp_async16(sb + (uint32_t)((row * ASH + c8) * 2),
                       &Ab[(long)row * K + k0 + c8]);
        }
        #pragma unroll
        for (int i = 0; i < 2; i++) {          // B: 512 chunks
            int v = tid + i * 256;
            int kr = v >> 4, c8 = (v & 15) * 8;
            cp_async16(sb + (uint32_t)A_BYTES + (uint32_t)((kr * BSH + c8) * 2),
                       &Xb[(long)(k0 + kr) * N + c8]);
        }
        cp_commit();
    };

    // prologue: stages 0..2 in flight (3 groups)
    load_stage(0);
    load_stage(1);
    load_stage(2);

    for (int it = 0; it < niter; it++) {
        // wait until stage it is resident: allow (groups in flight - 1) pending
        int rem = niter - 1 - it;              // stages still to be consumed after it
        if (rem >= 2) cp_wait<2>();
        else if (rem == 1) cp_wait<1>();
        else cp_wait<0>();
        __syncthreads();                        // publish stage it; orders prior reads

        if (it + 3 < niter) load_stage(it + 3); // overwrites stage read at it-1 (safe)

        const uint32_t sb = smem0 + (it % NSTAGE) * STAGE_BYTES;

        #pragma unroll
        for (int kk = 0; kk < 2; kk++) {
            uint32_t afr[4][4], bfr[4][2];
            #pragma unroll
            for (int mt = 0; mt < 4; mt++)
                ldsm_x4(afr[mt], sb + a_ldsm
                        + (uint32_t)((mt * 16 * ASH + kk * 16) * 2));
            #pragma unroll
            for (int p = 0; p < 2; p++) {
                uint32_t r4[4];
                ldsm_x4_trans(r4, sb + b_ldsm
                              + (uint32_t)((kk * 16 * BSH + p * 16) * 2));
                bfr[2 * p][0] = r4[0]; bfr[2 * p][1] = r4[1];
                bfr[2 * p + 1][0] = r4[2]; bfr[2 * p + 1][1] = r4[3];
            }
            #pragma unroll
            for (int mt = 0; mt < 4; mt++)
                #pragma unroll
                for (int nt = 0; nt < 4; nt++)
                    mma16n8k16(acc[mt][nt], afr[mt], bfr[nt]);
        }
    }

    if (MODE == 1) {
        const int ch0 = bm + warpM;
        if (ch0 < HID) {
            float mxA[4], mxB[4], scA[4], scB[4];
            #pragma unroll
            for (int nt = 0; nt < 4; nt++) {
                float a = -1e30f, bb = -1e30f;
                #pragma unroll
                for (int mt = 0; mt < 4; mt++) {
                    a  = fmaxf(a,  fmaxf(acc[mt][nt][0], acc[mt][nt][2]));
                    bb = fmaxf(bb, fmaxf(acc[mt][nt][1], acc[mt][nt][3]));
                }
                #pragma unroll
                for (int o = 4; o <= 16; o <<= 1) {
                    a  = fmaxf(a,  __shfl_xor_sync(0xffffffffu, a, o));
                    bb = fmaxf(bb, __shfl_xor_sync(0xffffffffu, bb, o));
                }
                mxA[nt] = a; mxB[nt] = bb;
            }
            #pragma unroll
            for (int nt = 0; nt < 4; nt++) {
                float sa = 0.f, sb2 = 0.f;
                #pragma unroll
                for (int mt = 0; mt < 4; mt++) {
                    acc[mt][nt][0] = __expf(acc[mt][nt][0] - mxA[nt]);
                    acc[mt][nt][2] = __expf(acc[mt][nt][2] - mxA[nt]);
                    sa += acc[mt][nt][0] + acc[mt][nt][2];
                    acc[mt][nt][1] = __expf(acc[mt][nt][1] - mxB[nt]);
                    acc[mt][nt][3] = __expf(acc[mt][nt][3] - mxB[nt]);
                    sb2 += acc[mt][nt][1] + acc[mt][nt][3];
                }
                #pragma unroll
                for (int o = 4; o <= 16; o <<= 1) {
                    sa  += __shfl_xor_sync(0xffffffffu, sa, o);
                    sb2 += __shfl_xor_sync(0xffffffffu, sb2, o);
                }
                scA[nt] = SCALE / sa; scB[nt] = SCALE / sb2;
            }
            __half* qb = q_out + (long)b * HID * T;
            #pragma unroll
            for (int mt = 0; mt < 4; mt++) {
                int ch = ch0 + mt * 16 + gid;
                #pragma unroll
                for (int nt = 0; nt < 4; nt++) {
                    int t = bn + warpN + nt * 8 + tg * 2;
                    *(__half2*)&qb[(long)ch * T + t] =
                        __floats2half2_rn(acc[mt][nt][0] * scA[nt],
                                          acc[mt][nt][1] * scB[nt]);
                    *(__half2*)&qb[(long)(ch + 8) * T + t] =
                        __floats2half2_rn(acc[mt][nt][2] * scA[nt],
                                          acc[mt][nt][3] * scB[nt]);
                }
            }
        } else {
            __half* dst = (ch0 < 2 * HID) ? k_out : v_out;
            const int chbase = ch0 - ((ch0 < 2 * HID) ? HID : 2 * HID);
            __half* db = dst + (long)b * HID * T;
            #pragma unroll
            for (int mt = 0; mt < 4; mt++) {
                int ch = chbase + mt * 16 + gid;
                #pragma unroll
                for (int nt = 0; nt < 4; nt++) {
                    int t = bn + warpN + nt * 8 + tg * 2;
                    *(__half2*)&db[(long)ch * T + t] =
                        __floats2half2_rn(acc[mt][nt][0], acc[mt][nt][1]);
                    *(__half2*)&db[(long)(ch + 8) * T + t] =
                        __floats2half2_rn(acc[mt][nt][2], acc[mt][nt][3]);
                }
            }
        }
    } else {
        // ---- GEMM2 epilogue: y fp16 + bias, GN partial sums (fp32) ----
        float ls = 0.f, lss = 0.f;
        __half* yb = q_out + (long)b * C * T;
        #pragma unroll
        for (int mt = 0; mt < 4; mt++) {
            int row0 = bm + warpM + mt * 16 + gid;
            float bv0 = bias[row0];
            float bv1 = bias[row0 + 8];
            #pragma unroll
            for (int nt = 0; nt < 4; nt++) {
                int col = bn + warpN + nt * 8 + tg * 2;
                float o0x = acc[mt][nt][0] + bv0, o0y = acc[mt][nt][1] + bv0;
                float o1x = acc[mt][nt][2] + bv1, o1y = acc[mt][nt][3] + bv1;
                ls  += o0x + o0y + o1x + o1y;
                lss += o0x * o0x + o0y * o0y + o1x * o1x + o1y * o1y;
                *(__half2*)&yb[(long)row0 * T + col] = __floats2half2_rn(o0x, o0y);
                *(__half2*)&yb[(long)(row0 + 8) * T + col] = __floats2half2_rn(o1x, o1y);
            }
        }
        float S  = blockReduceSum(ls, redsm);
        float SS = blockReduceSum(lss, redsm);
        if (tid == 0) {
            int tile = blockIdx.y * gridDim.x + blockIdx.x;   // < 128
            stats[((long)b * 128 + tile) * 2 + 0] = S;
            stats[((long)b * 128 + tile) * 2 + 1] = SS;
        }
    }
}

// ================= HMMA context: ctx[b,h] = k @ v^T (64x64) ================
#define CT 64
#define CROW 72
#define CTILE_BYTES (DH * CROW * 2)        // 9216
#define CSTAGE_BYTES (2 * CTILE_BYTES)     // 18432
#define CSTAGES 4
#define CTX_SMEM (CSTAGES * CSTAGE_BYTES)  // 73728

__global__ __launch_bounds__(256, 1)
void ctx_hmma(const __half* __restrict__ kh, const __half* __restrict__ vh,
              float* __restrict__ ctx)
{
    extern __shared__ char dsm[];
    const int tid = threadIdx.x;
    const int wid = tid >> 5;
    const int lane = tid & 31;
    const int gid = lane >> 2;
    const int tg  = lane & 3;
    const int lg  = lane >> 3;
    const int lr  = lane & 7;
    const int bh = blockIdx.x;
    const int b = bh >> 3, h = bh & 7;
    const __half* kb = kh + ((long)b * HID + h * DH) * T;
    const __half* vb = vh + ((long)b * HID + h * DH) * T;

    const uint32_t smem0 = smem_u32(dsm);
    const int warpM = (wid >> 2) * 32;
    const int warpN = (wid & 3) * 16;

    const uint32_t a_base = (uint32_t)(((warpM + (lg & 1) * 8 + lr) * CROW
                                        + (lg >> 1) * 8) * 2);
    const int brow = warpN + (lane & 7) + ((lane >> 4) << 3);
    const uint32_t b_base = (uint32_t)CTILE_BYTES
        + (uint32_t)((brow * CROW + ((lane >> 3) & 1) * 8) * 2);

    float acc[2][2][4];
    #pragma unroll
    for (int mi = 0; mi < 2; mi++)
        #pragma unroll
        for (int ni = 0; ni < 2; ni++)
            #pragma unroll
            for (int r = 0; r < 4; r++) acc[mi][ni][r] = 0.f;

    const int nchunks = T / CT;            // 64

    auto load = [&](int ch) {
        const int t0 = ch * CT;
        const uint32_t sb = smem0 + (ch % CSTAGES) * CSTAGE_BYTES;
        #pragma unroll
        for (int i = 0; i < 4; i++) {
            int v = tid + i * 256;
            int mat = v >> 9;
            int r = (v >> 3) & 63;
            int c8 = (v & 7) * 8;
            const __half* gp = (mat ? vb : kb) + (long)r * T + t0 + c8;
            cp_async16(sb + (uint32_t)(mat * CTILE_BYTES + r * (CROW * 2) + c8 * 2),
                       gp);
        }
        cp_commit();
    };

    load(0); load(1); load(2);

    for (int ch = 0; ch < nchunks; ch++) {
        int rem = nchunks - 1 - ch;
        if (rem >= 2) cp_wait<2>();
        else if (rem == 1) cp_wait<1>();
        else cp_wait<0>();
        __syncthreads();

        if (ch + 3 < nchunks) load(ch + 3);

        const uint32_t sb = smem0 + (ch % CSTAGES) * CSTAGE_BYTES;
        #pragma unroll
        for (int kk = 0; kk < 4; kk++) {
            uint32_t afr[2][4], bfr4[4];
            #pragma unroll
            for (int mi = 0; mi < 2; mi++)
                ldsm_x4(afr[mi], sb + a_base
                        + (uint32_t)((mi * 16 * CROW + kk * 16) * 2));
            ldsm_x4(bfr4, sb + b_base + (uint32_t)(kk * 16 * 2));
            #pragma unroll
            for (int mi = 0; mi < 2; mi++) {
                mma16n8k16(acc[mi][0], afr[mi], &bfr4[0]);
                mma16n8k16(acc[mi][1], afr[mi], &bfr4[2]);
            }
        }
    }

    float* cp = ctx + (long)bh * (DH * DH);
    #pragma unroll
    for (int mi = 0; mi < 2; mi++) {
        int d0 = warpM + mi * 16 + gid;
        #pragma unroll
        for (int ni = 0; ni < 2; ni++) {
            int e = warpN + ni * 8 + tg * 2;
            *(float2*)&cp[d0 * DH + e]       = make_float2(acc[mi][ni][0], acc[mi][ni][1]);
            *(float2*)&cp[(d0 + 8) * DH + e] = make_float2(acc[mi][ni][2], acc[mi][ni][3]);
        }
    }
}

// --------------------- fp32 -> fp16 convert pass ----------------------------
__global__ __launch_bounds__(256)
void conv_half(const float* __restrict__ in, __half* __restrict__ out, int n4)
{
    int i = blockIdx.x * 256 + threadIdx.x;
    if (i >= n4) return;
    float4 v = ((const float4*)in)[i];
    ((__half2*)out)[2 * i]     = __floats2half2_rn(v.x, v.y);
    ((__half2*)out)[2 * i + 1] = __floats2half2_rn(v.z, v.w);
}

// --------------------- softmax over time dim (k), fp16 in/out ---------------
__global__ __launch_bounds__(256)
void softmax_k(__half* __restrict__ kh)
{
    __shared__ float sm[32];
    int r = blockIdx.x;              // b*512 + c
    int b = r >> 9, c = r & 511;
    __half2* row = (__half2*)(kh + ((long)b * HID + c) * T);
    int tid = threadIdx.x;

    float v[16];
    float mx = -1e30f;
    #pragma unroll
    for (int i = 0; i < 8; i++) {
        float2 f = __half22float2(row[tid + i * 256]);
        v[2 * i] = f.x; v[2 * i + 1] = f.y;
        mx = fmaxf(mx, fmaxf(f.x, f.y));
    }
    mx = blockReduceMax(mx, sm);
    float s = 0.f;
    #pragma unroll
    for (int i = 0; i < 16; i++) { v[i] = __expf(v[i] - mx); s += v[i]; }
    s = blockReduceSum(s, sm);
    float inv = 1.f / s;
    #pragma unroll
    for (int i = 0; i < 8; i++)
        row[tid + i * 256] = __floats2half2_rn(v[2 * i] * inv, v[2 * i + 1] * inv);
}

// ----- Weff[b][o][h*64+d] = sum_e Wout[o][h*64+e] * ctx[b][h][d][e] -> half --
__global__ __launch_bounds__(256)
void make_weff(const float* __restrict__ ctx, const float* __restrict__ Wout,
               __half* __restrict__ weffh)
{
    __shared__ float cs[DH][DH];   // ctx[d][e]
    int b = blockIdx.x, h = blockIdx.y;
    const float* c = ctx + (long)(b * H + h) * (DH * DH);
    for (int i = threadIdx.x; i < DH * DH; i += 256) cs[i >> 6][i & 63] = c[i];
    __syncthreads();

    #pragma unroll
    for (int oo = 0; oo < 2; oo++) {
        int o = threadIdx.x + oo * 256;
        float w[DH];
        #pragma unroll
        for (int e = 0; e < DH; e++) w[e] = Wout[(long)o * C + h * DH + e];
        for (int d = 0; d < DH; d++) {
            float s = 0.f;
            #pragma unroll
            for (int e = 0; e < DH; e++) s = fmaf(w[e], cs[d][e], s);
            weffh[((long)b * C + o) * C + h * DH + d] = __float2half(s);
        }
    }
}

// --------------------- GroupNorm finalize + normalize -----------------------
__global__ __launch_bounds__(128)
void gn_finalize(const float* __restrict__ stats, float* __restrict__ mr)
{
    __shared__ float sm[32];
    int b = blockIdx.x;
    float s  = stats[(b * 128 + threadIdx.x) * 2 + 0];
    float ss = stats[(b * 128 + threadIdx.x) * 2 + 1];
    float S  = blockReduceSum(s, sm);
    float SS = blockReduceSum(ss, sm);
    if (threadIdx.x == 0) {
        const float n = (float)((long)C * T);
        float mean = S / n;
        float var  = SS / n - mean * mean;
        mr[b * 2 + 0] = mean;
        mr[b * 2 + 1] = rsqrtf(var + GN_EPS);
    }
}

__global__ __launch_bounds__(256)
void gn_norm(const __half* __restrict__ yh, const float* __restrict__ mr,
             const float* __restrict__ gw, const float* __restrict__ gb,
             float* __restrict__ out)
{
    int b = blockIdx.y;
    long base = (long)b * C * T;
    int idx = (blockIdx.x * 256 + threadIdx.x) * 4;
    int c = idx >> 12;                 // / 4096
    float mean = mr[b * 2 + 0], rstd = mr[b * 2 + 1];
    float g   = gw[c] * rstd;
    float beta = gb[c] - mean * g;
    float2 f0 = __half22float2(*(const __half2*)&yh[base + idx]);
    float2 f1 = __half22float2(*(const __half2*)&yh[base + idx + 2]);
    float4 v;
    v.x = fmaf(f0.x, g, beta);
    v.y = fmaf(f0.y, g, beta);
    v.z = fmaf(f1.x, g, beta);
    v.w = fmaf(f1.y, g, beta);
    *(float4*)&out[base + idx] = v;
}

// ---------------------------------------------------------------------------
extern "C" void kernel_launch(void* const* d_in, const int* in_sizes, int n_in,
                              void* d_out, int out_size)
{
    const float* x     = (const float*)d_in[0];
    const float* Wqkv  = (const float*)d_in[1];
    const float* Wout  = (const float*)d_in[2];
    const float* bout  = (const float*)d_in[3];
    const float* gnw   = (const float*)d_in[4];
    const float* gnb   = (const float*)d_in[5];
    float* out = (float*)d_out;

    float *ctx, *stats, *mr;
    __half *xh, *qh, *kh, *vh, *wqkvh, *weffh;
    cudaGetSymbolAddress((void**)&ctx,   g_ctx);
    cudaGetSymbolAddress((void**)&stats, g_stats);
    cudaGetSymbolAddress((void**)&mr,    g_mr);
    cudaGetSymbolAddress((void**)&xh,    g_xh);
    cudaGetSymbolAddress((void**)&qh,    g_qh);
    cudaGetSymbolAddress((void**)&kh,    g_kh);
    cudaGetSymbolAddress((void**)&vh,    g_vh);
    cudaGetSymbolAddress((void**)&wqkvh, g_wqkvh);
    cudaGetSymbolAddress((void**)&weffh, g_weffh);

    __half* yh = xh;   // xh dead after GEMM1; reuse as fp16 y

    cudaFuncSetAttribute(hgemm<1>,
                         cudaFuncAttributeMaxDynamicSharedMemorySize, TGEMM_SMEM);
    cudaFuncSetAttribute(hgemm<2>,
                         cudaFuncAttributeMaxDynamicSharedMemorySize, TGEMM_SMEM);
    cudaFuncSetAttribute(ctx_hmma,
                         cudaFuncAttributeMaxDynamicSharedMemorySize, CTX_SMEM);

    // side stream for GEMM1_q || (softmax_k -> ctx -> weff); serial fallback
    cudaStream_t s2 = 0;
    cudaEvent_t evA = 0, evB = 0;
    bool forked = (cudaStreamCreateWithFlags(&s2, cudaStreamNonBlocking) == cudaSuccess);
    if (forked) forked = (cudaEventCreateWithFlags(&evA, cudaEventDisableTiming) == cudaSuccess);
    if (forked) forked = (cudaEventCreateWithFlags(&evB, cudaEventDisableTiming) == cudaSuccess);

    // 0) convert inputs to fp16
    conv_half<<<(B * C * T / 4 + 255) / 256, 256>>>(x, xh, B * C * T / 4);
    conv_half<<<(QKV_CH * C / 4 + 255) / 256, 256>>>(Wqkv, wqkvh, QKV_CH * C / 4);

    // 1a) k/v portion of qkv GEMM (channels 512..1535)
    hgemm<1><<<dim3(T / BN, 8, B), 256, TGEMM_SMEM>>>(
        wqkvh, 0L, xh, (long)C * T, HID,
        QKV_CH, T, C, nullptr, qh, kh, vh, nullptr);

    if (forked) {
        cudaEventRecord(evA, 0);
        cudaStreamWaitEvent(s2, evA, 0);
        hgemm<1><<<dim3(T / BN, 4, B), 256, TGEMM_SMEM, s2>>>(
            wqkvh, 0L, xh, (long)C * T, 0,
            QKV_CH, T, C, nullptr, qh, kh, vh, nullptr);
        cudaEventRecord(evB, s2);
    } else {
        hgemm<1><<<dim3(T / BN, 4, B), 256, TGEMM_SMEM>>>(
            wqkvh, 0L, xh, (long)C * T, 0,
            QKV_CH, T, C, nullptr, qh, kh, vh, nullptr);
    }

    // 2-4) k chain (depends only on kh/vh)
    softmax_k<<<B * HID, 256>>>(kh);
    ctx_hmma<<<B * H, 256, CTX_SMEM>>>(kh, vh, ctx);
    make_weff<<<dim3(B, H), 256>>>(ctx, Wout, weffh);

    if (forked) cudaStreamWaitEvent(0, evB, 0);

    // 5) y = Weff @ q + b_out (fp16 y into reused xh), fused GN partial stats
    hgemm<2><<<dim3(T / BN, C / BM, B), 256, TGEMM_SMEM>>>(
        weffh, (long)C * C, qh, (long)HID * T, 0,
        C, T, C, bout, yh, nullptr, nullptr, stats);

    // 6) GroupNorm finalize + apply
    gn_finalize<<<B, 128>>>(stats, mr);
    gn_norm<<<dim3((C * T) / 1024, B), 256>>>(yh, mr, gnw, gnb, out);
}

// round 17
// speedup vs baseline: 1.2489x; 1.0324x over previous
#include <cuda_runtime.h>
#include <cuda_fp16.h>
#include <cstdint>

// ---------------------------------------------------------------------------
// LinearAttention fused pipeline (fp16 HMMA GEMMs + HMMA ctx, fused softmax_q
// + GN stats; stream-forked GEMM1_q || softmax_k->ctx->weff chain).
// GEMM tile 128x128xBK64, occupancy 2, 3-stage cp.async, ONE barrier per iter
// (8 barrier waves per tile; prefetch distance ~1.5 iters).
// b=16, c=512, t=4096, heads=8, dh=64, hidden=512
// ---------------------------------------------------------------------------

#define B   16
#define C   512
#define T   4096
#define H   8
#define DH  64
#define HID 512
#define QKV_CH 1536
#define SCALE 0.125f   // 64^-0.5
#define GN_EPS 1e-5f

// Scratch (static device arrays: allocation-free rule)
__device__ __half g_xh[(size_t)B * C * T];                // 67 MB (xh, then y fp16)
__device__ __half g_qh[(size_t)B * HID * T];              // 67 MB (softmaxed q)
__device__ __half g_kh[(size_t)B * HID * T];              // 67 MB
__device__ __half g_vh[(size_t)B * HID * T];              // 67 MB
__device__ __half g_wqkvh[(size_t)QKV_CH * C];            // 1.5 MB
__device__ __half g_weffh[(size_t)B * C * C];             // 8 MB
__device__ float  g_ctx[(size_t)B * H * DH * DH];         // 2 MB
__device__ float  g_stats[B * 128 * 2];
__device__ float  g_mr[B * 2];

// ========================= helpers =========================================
__device__ __forceinline__ uint32_t smem_u32(const void* p) {
    uint32_t a;
    asm("{ .reg .u64 t; cvta.to.shared.u64 t, %1; cvt.u32.u64 %0, t; }"
        : "=r"(a) : "l"(p));
    return a;
}

__device__ __forceinline__ void cp_async16(uint32_t smem_dst, const void* gsrc) {
    asm volatile("cp.async.cg.shared.global [%0], [%1], 16;"
                 :: "r"(smem_dst), "l"(gsrc));
}
__device__ __forceinline__ void cp_commit() {
    asm volatile("cp.async.commit_group;" ::: "memory");
}
template <int N>
__device__ __forceinline__ void cp_wait() {
    asm volatile("cp.async.wait_group %0;" :: "n"(N) : "memory");
}

__device__ __forceinline__ void ldsm_x4(uint32_t* r, uint32_t addr) {
    asm volatile("ldmatrix.sync.aligned.m8n8.x4.shared.b16 {%0,%1,%2,%3}, [%4];"
                 : "=r"(r[0]), "=r"(r[1]), "=r"(r[2]), "=r"(r[3]) : "r"(addr));
}
__device__ __forceinline__ void ldsm_x4_trans(uint32_t* r, uint32_t addr) {
    asm volatile("ldmatrix.sync.aligned.m8n8.x4.trans.shared.b16 {%0,%1,%2,%3}, [%4];"
                 : "=r"(r[0]), "=r"(r[1]), "=r"(r[2]), "=r"(r[3]) : "r"(addr));
}

__device__ __forceinline__ void mma16n8k16(float* c, const uint32_t* a,
                                           const uint32_t* b) {
    asm volatile(
        "mma.sync.aligned.m16n8k16.row.col.f32.f16.f16.f32 "
        "{%0,%1,%2,%3}, {%4,%5,%6,%7}, {%8,%9}, {%0,%1,%2,%3};"
        : "+f"(c[0]), "+f"(c[1]), "+f"(c[2]), "+f"(c[3])
        : "r"(a[0]), "r"(a[1]), "r"(a[2]), "r"(a[3]),
          "r"(b[0]), "r"(b[1]));
}

// ------------------------- block reduce helper -----------------------------
__device__ __forceinline__ float blockReduceSum(float v, float* sm) {
    __syncthreads();
    #pragma unroll
    for (int o = 16; o; o >>= 1) v += __shfl_down_sync(0xffffffffu, v, o);
    int lane = threadIdx.x & 31, w = threadIdx.x >> 5;
    if (lane == 0) sm[w] = v;
    __syncthreads();
    if (w == 0) {
        v = (lane < (int)(blockDim.x >> 5)) ? sm[lane] : 0.f;
        #pragma unroll
        for (int o = 16; o; o >>= 1) v += __shfl_down_sync(0xffffffffu, v, o);
        if (lane == 0) sm[0] = v;
    }
    __syncthreads();
    return sm[0];
}

__device__ __forceinline__ float blockReduceMax(float v, float* sm) {
    __syncthreads();
    #pragma unroll
    for (int o = 16; o; o >>= 1) v = fmaxf(v, __shfl_down_sync(0xffffffffu, v, o));
    int lane = threadIdx.x & 31, w = threadIdx.x >> 5;
    if (lane == 0) sm[w] = v;
    __syncthreads();
    if (w == 0) {
        v = (lane < (int)(blockDim.x >> 5)) ? sm[lane] : -1e30f;
        #pragma unroll
        for (int o = 16; o; o >>= 1) v = fmaxf(v, __shfl_down_sync(0xffffffffu, v, o));
        if (lane == 0) sm[0] = v;
    }
    __syncthreads();
    return sm[0];
}

// ========================= fp16 HMMA GEMM ==================================
// Tile 128x128x64, 8 warps (2m x 4n) of 64x32, 3-stage cp.async, occupancy 2,
// ONE __syncthreads per K-iter (8 per tile).
#define BM 128
#define BN 128
#define BK 64
#define ASH 72     // halves per A row (64 + pad 8)
#define BSH 136    // halves per B row (128 + pad 8)
#define A_BYTES (BM * ASH * 2)            // 18432
#define B_BYTES (BK * BSH * 2)            // 17408
#define STAGE_BYTES (A_BYTES + B_BYTES)   // 35840
#define NSTAGE 3
#define TGEMM_SMEM (NSTAGE * STAGE_BYTES) // 107520

// MODE 1: qkv epilogue (q softmax -> qh, k/v -> kh/vh), rows offset by bm0.
// MODE 2: y fp16 -> q_out, bias, GN partial stats.
template <int MODE>
__global__ __launch_bounds__(256, 2)
void hgemm(const __half* __restrict__ A, long strideA,
           const __half* __restrict__ X, long strideX,
           int bm0,
           int M, int N, int K, const float* __restrict__ bias,
           __half* __restrict__ q_out, __half* __restrict__ k_out,
           __half* __restrict__ v_out, float* __restrict__ stats)
{
    extern __shared__ char dsm[];
    __shared__ float redsm[32];
    const int tid = threadIdx.x;
    const int wid = tid >> 5;
    const int lane = tid & 31;
    const int gid = lane >> 2;
    const int tg  = lane & 3;
    const int lg  = lane >> 3;
    const int lr  = lane & 7;
    const int b  = blockIdx.z;
    const int bm = bm0 + blockIdx.y * BM, bn = blockIdx.x * BN;
    const __half* Ab = A + (long)b * strideA + (long)bm * K;
    const __half* Xb = X + (long)b * strideX + bn;

    const uint32_t smem0 = smem_u32(dsm);
    const int warpM = (wid >> 2) * 64;     // 0 or 64
    const int warpN = (wid & 3) * 32;      // 0,32,64,96

    const uint32_t a_ldsm = (uint32_t)(((warpM + (lg & 1) * 8 + lr) * ASH
                                        + (lg >> 1) * 8) * 2);
    const uint32_t b_ldsm = (uint32_t)A_BYTES
        + (uint32_t)((((lg & 1) * 8 + lr) * BSH + warpN + (lg >> 1) * 8) * 2);

    float acc[4][4][4];
    #pragma unroll
    for (int mt = 0; mt < 4; mt++)
        #pragma unroll
        for (int nt = 0; nt < 4; nt++)
            #pragma unroll
            for (int r = 0; r < 4; r++) acc[mt][nt][r] = 0.f;

    const int niter = K / BK;   // 8

    auto load_stage = [&](int it) {
        const int k0 = it * BK;
        const uint32_t sb = smem0 + (it % NSTAGE) * STAGE_BYTES;
        #pragma unroll
        for (int i = 0; i < 4; i++) {          // A: 1024 chunks of 8 halves
            int v = tid + i * 256;
            int row = v >> 3, c8 = (v & 7) * 8;
            cp_async16(sb + (uint32_t)((row * ASH + c8) * 2),
                       &Ab[(long)row * K + k0 + c8]);
        }
        #pragma unroll
        for (int i = 0; i < 4; i++) {          // B: 1024 chunks
            int v = tid + i * 256;
            int kr = v >> 4, c8 = (v & 15) * 8;
            cp_async16(sb + (uint32_t)A_BYTES + (uint32_t)((kr * BSH + c8) * 2),
                       &Xb[(long)(k0 + kr) * N + c8]);
        }
        cp_commit();
    };

    // prologue: stages 0..1 in flight (2 groups)
    load_stage(0);
    load_stage(1);

    for (int it = 0; it < niter; it++) {
        if (it + 1 < niter) cp_wait<1>();      // stage it resident
        else cp_wait<0>();
        __syncthreads();                        // publish stage it; orders reads

        if (it + 2 < niter) load_stage(it + 2); // overwrites stage read at it-1

        const uint32_t sb = smem0 + (it % NSTAGE) * STAGE_BYTES;

        #pragma unroll
        for (int kk = 0; kk < 4; kk++) {
            uint32_t afr[4][4], bfr[4][2];
            #pragma unroll
            for (int mt = 0; mt < 4; mt++)
                ldsm_x4(afr[mt], sb + a_ldsm
                        + (uint32_t)((mt * 16 * ASH + kk * 16) * 2));
            #pragma unroll
            for (int p = 0; p < 2; p++) {
                uint32_t r4[4];
                ldsm_x4_trans(r4, sb + b_ldsm
                              + (uint32_t)((kk * 16 * BSH + p * 16) * 2));
                bfr[2 * p][0] = r4[0]; bfr[2 * p][1] = r4[1];
                bfr[2 * p + 1][0] = r4[2]; bfr[2 * p + 1][1] = r4[3];
            }
            #pragma unroll
            for (int mt = 0; mt < 4; mt++)
                #pragma unroll
                for (int nt = 0; nt < 4; nt++)
                    mma16n8k16(acc[mt][nt], afr[mt], bfr[nt]);
        }
    }

    if (MODE == 1) {
        const int ch0 = bm + warpM;
        if (ch0 < HID) {
            float mxA[4], mxB[4], scA[4], scB[4];
            #pragma unroll
            for (int nt = 0; nt < 4; nt++) {
                float a = -1e30f, bb = -1e30f;
                #pragma unroll
                for (int mt = 0; mt < 4; mt++) {
                    a  = fmaxf(a,  fmaxf(acc[mt][nt][0], acc[mt][nt][2]));
                    bb = fmaxf(bb, fmaxf(acc[mt][nt][1], acc[mt][nt][3]));
                }
                #pragma unroll
                for (int o = 4; o <= 16; o <<= 1) {
                    a  = fmaxf(a,  __shfl_xor_sync(0xffffffffu, a, o));
                    bb = fmaxf(bb, __shfl_xor_sync(0xffffffffu, bb, o));
                }
                mxA[nt] = a; mxB[nt] = bb;
            }
            #pragma unroll
            for (int nt = 0; nt < 4; nt++) {
                float sa = 0.f, sb2 = 0.f;
                #pragma unroll
                for (int mt = 0; mt < 4; mt++) {
                    acc[mt][nt][0] = __expf(acc[mt][nt][0] - mxA[nt]);
                    acc[mt][nt][2] = __expf(acc[mt][nt][2] - mxA[nt]);
                    sa += acc[mt][nt][0] + acc[mt][nt][2];
                    acc[mt][nt][1] = __expf(acc[mt][nt][1] - mxB[nt]);
                    acc[mt][nt][3] = __expf(acc[mt][nt][3] - mxB[nt]);
                    sb2 += acc[mt][nt][1] + acc[mt][nt][3];
                }
                #pragma unroll
                for (int o = 4; o <= 16; o <<= 1) {
                    sa  += __shfl_xor_sync(0xffffffffu, sa, o);
                    sb2 += __shfl_xor_sync(0xffffffffu, sb2, o);
                }
                scA[nt] = SCALE / sa; scB[nt] = SCALE / sb2;
            }
            __half* qb = q_out + (long)b * HID * T;
            #pragma unroll
            for (int mt = 0; mt < 4; mt++) {
                int ch = ch0 + mt * 16 + gid;
                #pragma unroll
                for (int nt = 0; nt < 4; nt++) {
                    int t = bn + warpN + nt * 8 + tg * 2;
                    *(__half2*)&qb[(long)ch * T + t] =
                        __floats2half2_rn(acc[mt][nt][0] * scA[nt],
                                          acc[mt][nt][1] * scB[nt]);
                    *(__half2*)&qb[(long)(ch + 8) * T + t] =
                        __floats2half2_rn(acc[mt][nt][2] * scA[nt],
                                          acc[mt][nt][3] * scB[nt]);
                }
            }
        } else {
            __half* dst = (ch0 < 2 * HID) ? k_out : v_out;
            const int chbase = ch0 - ((ch0 < 2 * HID) ? HID : 2 * HID);
            __half* db = dst + (long)b * HID * T;
            #pragma unroll
            for (int mt = 0; mt < 4; mt++) {
                int ch = chbase + mt * 16 + gid;
                #pragma unroll
                for (int nt = 0; nt < 4; nt++) {
                    int t = bn + warpN + nt * 8 + tg * 2;
                    *(__half2*)&db[(long)ch * T + t] =
                        __floats2half2_rn(acc[mt][nt][0], acc[mt][nt][1]);
                    *(__half2*)&db[(long)(ch + 8) * T + t] =
                        __floats2half2_rn(acc[mt][nt][2], acc[mt][nt][3]);
                }
            }
        }
    } else {
        // ---- GEMM2 epilogue: y fp16 + bias, GN partial sums (fp32) ----
        float ls = 0.f, lss = 0.f;
        __half* yb = q_out + (long)b * C * T;
        #pragma unroll
        for (int mt = 0; mt < 4; mt++) {
            int row0 = bm + warpM + mt * 16 + gid;
            float bv0 = bias[row0];
            float bv1 = bias[row0 + 8];
            #pragma unroll
            for (int nt = 0; nt < 4; nt++) {
                int col = bn + warpN + nt * 8 + tg * 2;
                float o0x = acc[mt][nt][0] + bv0, o0y = acc[mt][nt][1] + bv0;
                float o1x = acc[mt][nt][2] + bv1, o1y = acc[mt][nt][3] + bv1;
                ls  += o0x + o0y + o1x + o1y;
                lss += o0x * o0x + o0y * o0y + o1x * o1x + o1y * o1y;
                *(__half2*)&yb[(long)row0 * T + col] = __floats2half2_rn(o0x, o0y);
                *(__half2*)&yb[(long)(row0 + 8) * T + col] = __floats2half2_rn(o1x, o1y);
            }
        }
        float S  = blockReduceSum(ls, redsm);
        float SS = blockReduceSum(lss, redsm);
        if (tid == 0) {
            int tile = blockIdx.y * gridDim.x + blockIdx.x;   // < 128
            stats[((long)b * 128 + tile) * 2 + 0] = S;
            stats[((long)b * 128 + tile) * 2 + 1] = SS;
        }
    }
}

// ================= HMMA context: ctx[b,h] = k @ v^T (64x64) ================
#define CT 64
#define CROW 72
#define CTILE_BYTES (DH * CROW * 2)        // 9216
#define CSTAGE_BYTES (2 * CTILE_BYTES)     // 18432
#define CSTAGES 4
#define CTX_SMEM (CSTAGES * CSTAGE_BYTES)  // 73728

__global__ __launch_bounds__(256, 1)
void ctx_hmma(const __half* __restrict__ kh, const __half* __restrict__ vh,
              float* __restrict__ ctx)
{
    extern __shared__ char dsm[];
    const int tid = threadIdx.x;
    const int wid = tid >> 5;
    const int lane = tid & 31;
    const int gid = lane >> 2;
    const int tg  = lane & 3;
    const int lg  = lane >> 3;
    const int lr  = lane & 7;
    const int bh = blockIdx.x;
    const int b = bh >> 3, h = bh & 7;
    const __half* kb = kh + ((long)b * HID + h * DH) * T;
    const __half* vb = vh + ((long)b * HID + h * DH) * T;

    const uint32_t smem0 = smem_u32(dsm);
    const int warpM = (wid >> 2) * 32;
    const int warpN = (wid & 3) * 16;

    const uint32_t a_base = (uint32_t)(((warpM + (lg & 1) * 8 + lr) * CROW
                                        + (lg >> 1) * 8) * 2);
    const int brow = warpN + (lane & 7) + ((lane >> 4) << 3);
    const uint32_t b_base = (uint32_t)CTILE_BYTES
        + (uint32_t)((brow * CROW + ((lane >> 3) & 1) * 8) * 2);

    float acc[2][2][4];
    #pragma unroll
    for (int mi = 0; mi < 2; mi++)
        #pragma unroll
        for (int ni = 0; ni < 2; ni++)
            #pragma unroll
            for (int r = 0; r < 4; r++) acc[mi][ni][r] = 0.f;

    const int nchunks = T / CT;            // 64

    auto load = [&](int ch) {
        const int t0 = ch * CT;
        const uint32_t sb = smem0 + (ch % CSTAGES) * CSTAGE_BYTES;
        #pragma unroll
        for (int i = 0; i < 4; i++) {
            int v = tid + i * 256;
            int mat = v >> 9;
            int r = (v >> 3) & 63;
            int c8 = (v & 7) * 8;
            const __half* gp = (mat ? vb : kb) + (long)r * T + t0 + c8;
            cp_async16(sb + (uint32_t)(mat * CTILE_BYTES + r * (CROW * 2) + c8 * 2),
                       gp);
        }
        cp_commit();
    };

    load(0); load(1); load(2);

    for (int ch = 0; ch < nchunks; ch++) {
        int rem = nchunks - 1 - ch;
        if (rem >= 2) cp_wait<2>();
        else if (rem == 1) cp_wait<1>();
        else cp_wait<0>();
        __syncthreads();

        if (ch + 3 < nchunks) load(ch + 3);

        const uint32_t sb = smem0 + (ch % CSTAGES) * CSTAGE_BYTES;
        #pragma unroll
        for (int kk = 0; kk < 4; kk++) {
            uint32_t afr[2][4], bfr4[4];
            #pragma unroll
            for (int mi = 0; mi < 2; mi++)
                ldsm_x4(afr[mi], sb + a_base
                        + (uint32_t)((mi * 16 * CROW + kk * 16) * 2));
            ldsm_x4(bfr4, sb + b_base + (uint32_t)(kk * 16 * 2));
            #pragma unroll
            for (int mi = 0; mi < 2; mi++) {
                mma16n8k16(acc[mi][0], afr[mi], &bfr4[0]);
                mma16n8k16(acc[mi][1], afr[mi], &bfr4[2]);
            }
        }
    }

    float* cp = ctx + (long)bh * (DH * DH);
    #pragma unroll
    for (int mi = 0; mi < 2; mi++) {
        int d0 = warpM + mi * 16 + gid;
        #pragma unroll
        for (int ni = 0; ni < 2; ni++) {
            int e = warpN + ni * 8 + tg * 2;
            *(float2*)&cp[d0 * DH + e]       = make_float2(acc[mi][ni][0], acc[mi][ni][1]);
            *(float2*)&cp[(d0 + 8) * DH + e] = make_float2(acc[mi][ni][2], acc[mi][ni][3]);
        }
    }
}

// --------------------- fp32 -> fp16 convert pass ----------------------------
__global__ __launch_bounds__(256)
void conv_half(const float* __restrict__ in, __half* __restrict__ out, int n4)
{
    int i = blockIdx.x * 256 + threadIdx.x;
    if (i >= n4) return;
    float4 v = ((const float4*)in)[i];
    ((__half2*)out)[2 * i]     = __floats2half2_rn(v.x, v.y);
    ((__half2*)out)[2 * i + 1] = __floats2half2_rn(v.z, v.w);
}

// --------------------- softmax over time dim (k), fp16 in/out ---------------
__global__ __launch_bounds__(256)
void softmax_k(__half* __restrict__ kh)
{
    __shared__ float sm[32];
    int r = blockIdx.x;              // b*512 + c
    int b = r >> 9, c = r & 511;
    __half2* row = (__half2*)(kh + ((long)b * HID + c) * T);
    int tid = threadIdx.x;

    float v[16];
    float mx = -1e30f;
    #pragma unroll
    for (int i = 0; i < 8; i++) {
        float2 f = __half22float2(row[tid + i * 256]);
        v[2 * i] = f.x; v[2 * i + 1] = f.y;
        mx = fmaxf(mx, fmaxf(f.x, f.y));
    }
    mx = blockReduceMax(mx, sm);
    float s = 0.f;
    #pragma unroll
    for (int i = 0; i < 16; i++) { v[i] = __expf(v[i] - mx); s += v[i]; }
    s = blockReduceSum(s, sm);
    float inv = 1.f / s;
    #pragma unroll
    for (int i = 0; i < 8; i++)
        row[tid + i * 256] = __floats2half2_rn(v[2 * i] * inv, v[2 * i + 1] * inv);
}

// ----- Weff[b][o][h*64+d] = sum_e Wout[o][h*64+e] * ctx[b][h][d][e] -> half --
__global__ __launch_bounds__(256)
void make_weff(const float* __restrict__ ctx, const float* __restrict__ Wout,
               __half* __restrict__ weffh)
{
    __shared__ float cs[DH][DH];   // ctx[d][e]
    int b = blockIdx.x, h = blockIdx.y;
    const float* c = ctx + (long)(b * H + h) * (DH * DH);
    for (int i = threadIdx.x; i < DH * DH; i += 256) cs[i >> 6][i & 63] = c[i];
    __syncthreads();

    #pragma unroll
    for (int oo = 0; oo < 2; oo++) {
        int o = threadIdx.x + oo * 256;
        float w[DH];
        #pragma unroll
        for (int e = 0; e < DH; e++) w[e] = Wout[(long)o * C + h * DH + e];
        for (int d = 0; d < DH; d++) {
            float s = 0.f;
            #pragma unroll
            for (int e = 0; e < DH; e++) s = fmaf(w[e], cs[d][e], s);
            weffh[((long)b * C + o) * C + h * DH + d] = __float2half(s);
        }
    }
}

// --------------------- GroupNorm finalize + normalize -----------------------
__global__ __launch_bounds__(128)
void gn_finalize(const float* __restrict__ stats, float* __restrict__ mr)
{
    __shared__ float sm[32];
    int b = blockIdx.x;
    float s  = stats[(b * 128 + threadIdx.x) * 2 + 0];
    float ss = stats[(b * 128 + threadIdx.x) * 2 + 1];
    float S  = blockReduceSum(s, sm);
    float SS = blockReduceSum(ss, sm);
    if (threadIdx.x == 0) {
        const float n = (float)((long)C * T);
        float mean = S / n;
        float var  = SS / n - mean * mean;
        mr[b * 2 + 0] = mean;
        mr[b * 2 + 1] = rsqrtf(var + GN_EPS);
    }
}

__global__ __launch_bounds__(256)
void gn_norm(const __half* __restrict__ yh, const float* __restrict__ mr,
             const float* __restrict__ gw, const float* __restrict__ gb,
             float* __restrict__ out)
{
    int b = blockIdx.y;
    long base = (long)b * C * T;
    int idx = (blockIdx.x * 256 + threadIdx.x) * 4;
    int c = idx >> 12;                 // / 4096
    float mean = mr[b * 2 + 0], rstd = mr[b * 2 + 1];
    float g   = gw[c] * rstd;
    float beta = gb[c] - mean * g;
    float2 f0 = __half22float2(*(const __half2*)&yh[base + idx]);
    float2 f1 = __half22float2(*(const __half2*)&yh[base + idx + 2]);
    float4 v;
    v.x = fmaf(f0.x, g, beta);
    v.y = fmaf(f0.y, g, beta);
    v.z = fmaf(f1.x, g, beta);
    v.w = fmaf(f1.y, g, beta);
    *(float4*)&out[base + idx] = v;
}

// ---------------------------------------------------------------------------
extern "C" void kernel_launch(void* const* d_in, const int* in_sizes, int n_in,
                              void* d_out, int out_size)
{
    const float* x     = (const float*)d_in[0];
    const float* Wqkv  = (const float*)d_in[1];
    const float* Wout  = (const float*)d_in[2];
    const float* bout  = (const float*)d_in[3];
    const float* gnw   = (const float*)d_in[4];
    const float* gnb   = (const float*)d_in[5];
    float* out = (float*)d_out;

    float *ctx, *stats, *mr;
    __half *xh, *qh, *kh, *vh, *wqkvh, *weffh;
    cudaGetSymbolAddress((void**)&ctx,   g_ctx);
    cudaGetSymbolAddress((void**)&stats, g_stats);
    cudaGetSymbolAddress((void**)&mr,    g_mr);
    cudaGetSymbolAddress((void**)&xh,    g_xh);
    cudaGetSymbolAddress((void**)&qh,    g_qh);
    cudaGetSymbolAddress((void**)&kh,    g_kh);
    cudaGetSymbolAddress((void**)&vh,    g_vh);
    cudaGetSymbolAddress((void**)&wqkvh, g_wqkvh);
    cudaGetSymbolAddress((void**)&weffh, g_weffh);

    __half* yh = xh;   // xh dead after GEMM1; reuse as fp16 y

    cudaFuncSetAttribute(hgemm<1>,
                         cudaFuncAttributeMaxDynamicSharedMemorySize, TGEMM_SMEM);
    cudaFuncSetAttribute(hgemm<2>,
                         cudaFuncAttributeMaxDynamicSharedMemorySize, TGEMM_SMEM);
    cudaFuncSetAttribute(ctx_hmma,
                         cudaFuncAttributeMaxDynamicSharedMemorySize, CTX_SMEM);

    // side stream for GEMM1_q || (softmax_k -> ctx -> weff); serial fallback
    cudaStream_t s2 = 0;
    cudaEvent_t evA = 0, evB = 0;
    bool forked = (cudaStreamCreateWithFlags(&s2, cudaStreamNonBlocking) == cudaSuccess);
    if (forked) forked = (cudaEventCreateWithFlags(&evA, cudaEventDisableTiming) == cudaSuccess);
    if (forked) forked = (cudaEventCreateWithFlags(&evB, cudaEventDisableTiming) == cudaSuccess);

    // 0) convert inputs to fp16
    conv_half<<<(B * C * T / 4 + 255) / 256, 256>>>(x, xh, B * C * T / 4);
    conv_half<<<(QKV_CH * C / 4 + 255) / 256, 256>>>(Wqkv, wqkvh, QKV_CH * C / 4);

    // 1a) k/v portion of qkv GEMM (channels 512..1535)
    hgemm<1><<<dim3(T / BN, 8, B), 256, TGEMM_SMEM>>>(
        wqkvh, 0L, xh, (long)C * T, HID,
        QKV_CH, T, C, nullptr, qh, kh, vh, nullptr);

    if (forked) {
        cudaEventRecord(evA, 0);
        cudaStreamWaitEvent(s2, evA, 0);
        hgemm<1><<<dim3(T / BN, 4, B), 256, TGEMM_SMEM, s2>>>(
            wqkvh, 0L, xh, (long)C * T, 0,
            QKV_CH, T, C, nullptr, qh, kh, vh, nullptr);
        cudaEventRecord(evB, s2);
    } else {
        hgemm<1><<<dim3(T / BN, 4, B), 256, TGEMM_SMEM>>>(
            wqkvh, 0L, xh, (long)C * T, 0,
            QKV_CH, T, C, nullptr, qh, kh, vh, nullptr);
    }

    // 2-4) k chain (depends only on kh/vh)
    softmax_k<<<B * HID, 256>>>(kh);
    ctx_hmma<<<B * H, 256, CTX_SMEM>>>(kh, vh, ctx);
    make_weff<<<dim3(B, H), 256>>>(ctx, Wout, weffh);

    if (forked) cudaStreamWaitEvent(0, evB, 0);

    // 5) y = Weff @ q + b_out (fp16 y into reused xh), fused GN partial stats
    hgemm<2><<<dim3(T / BN, C / BM, B), 256, TGEMM_SMEM>>>(
        weffh, (long)C * C, qh, (long)HID * T, 0,
        C, T, C, bout, yh, nullptr, nullptr, stats);

    // 6) GroupNorm finalize + apply
    gn_finalize<<<B, 128>>>(stats, mr);
    gn_norm<<<dim3((C * T) / 1024, B), 256>>>(yh, mr, gnw, gnb, out);
}